// round 1
// baseline (speedup 1.0000x reference)
#include <cuda_runtime.h>
#include <math.h>

// Problem constants
#define B_ 2
#define T_ 2048
#define C_ 1024
#define H_ 16
#define D_ 64
#define WIN_ 512

// Scratch (allocation-free: __device__ globals)
__device__ float g_Q[B_*H_*T_*D_];
__device__ float g_K[B_*H_*T_*D_];
__device__ float g_V[B_*H_*T_*D_];
__device__ float g_att[B_*T_*C_];

// ---------------------------------------------------------------------------
// SGEMM: C[m,n] = sum_k A[m,k] * W[n,k] + bias[n]
// MODE 0: A = x, W = W_qkv, scatter into g_Q/g_K/g_V ([B,H,T,d] layout)
// MODE 1: A = g_att (device global), W = W_proj, write d_out + bias
// 128x128 tile, BK=8, 256 threads, 8x8 micro-tile per thread.
// ---------------------------------------------------------------------------
template <int MODE>
__global__ __launch_bounds__(256) void sgemm_kernel(
    const float* __restrict__ A, const float* __restrict__ W,
    const float* __restrict__ bias, float* __restrict__ Cout,
    int M, int N, int K)
{
    __shared__ float As[8][128];
    __shared__ float Bs[8][128];

    const int tid = threadIdx.x;
    const int tx = tid & 15;        // 0..15 (n dir)
    const int ty = tid >> 4;        // 0..15 (m dir)
    const int bm = blockIdx.y;
    const int bn = blockIdx.x;

    const float* Ap = (MODE == 1) ? g_att : A;
    const float* Ablk = Ap + (size_t)(bm * 128) * K;
    const float* Wblk = W  + (size_t)(bn * 128) * K;

    const int lrow = tid >> 1;       // 0..127
    const int lcol = (tid & 1) * 4;  // 0 or 4

    float acc[8][8];
    #pragma unroll
    for (int i = 0; i < 8; i++)
        #pragma unroll
        for (int j = 0; j < 8; j++) acc[i][j] = 0.f;

    for (int k0 = 0; k0 < K; k0 += 8) {
        float4 av = *(const float4*)(Ablk + (size_t)lrow * K + k0 + lcol);
        float4 wv = *(const float4*)(Wblk + (size_t)lrow * K + k0 + lcol);
        __syncthreads();   // previous iter's reads done
        As[lcol + 0][lrow] = av.x; As[lcol + 1][lrow] = av.y;
        As[lcol + 2][lrow] = av.z; As[lcol + 3][lrow] = av.w;
        Bs[lcol + 0][lrow] = wv.x; Bs[lcol + 1][lrow] = wv.y;
        Bs[lcol + 2][lrow] = wv.z; Bs[lcol + 3][lrow] = wv.w;
        __syncthreads();

        #pragma unroll
        for (int k = 0; k < 8; k++) {
            float ra[8], rb[8];
            #pragma unroll
            for (int i = 0; i < 8; i++) ra[i] = As[k][ty * 8 + i];
            #pragma unroll
            for (int j = 0; j < 8; j++) rb[j] = Bs[k][tx * 8 + j];
            #pragma unroll
            for (int i = 0; i < 8; i++)
                #pragma unroll
                for (int j = 0; j < 8; j++)
                    acc[i][j] = fmaf(ra[i], rb[j], acc[i][j]);
        }
    }

    // Epilogue
    #pragma unroll
    for (int i = 0; i < 8; i++) {
        const int m = bm * 128 + ty * 8 + i;
        #pragma unroll
        for (int j = 0; j < 8; j++) {
            const int n = bn * 128 + tx * 8 + j;
            float v = acc[i][j] + bias[n];
            if (MODE == 0) {
                // n in [0,3072): sel = q/k/v, head, dim
                const int sel = n >> 10;
                const int r = n & 1023;
                const int h = r >> 6;
                const int dd = r & 63;
                const int b = m >> 11;   // T_ = 2048
                const int t = m & 2047;
                float* dst = (sel == 0) ? g_Q : ((sel == 1) ? g_K : g_V);
                dst[(((size_t)(b * H_ + h)) * T_ + t) * D_ + dd] = v;
            } else {
                Cout[(size_t)m * N + n] = v;
            }
        }
    }
}

// ---------------------------------------------------------------------------
// Attention: 64 q-rows per block, 64-key tiles, fp32.
// Softcap bounds scores to (-30,30] -> fixed softmax max of 30 (no rescaling).
// Thread layout: 256 threads = 64 rows x 4 quad-lanes; each lane owns a
// 16-dim slice of q and of the output accumulator.
// ---------------------------------------------------------------------------
__global__ __launch_bounds__(256) void attn_kernel(const int* __restrict__ spl)
{
    __shared__ float Ksm[64][64];
    __shared__ float Vsm[64][64];

    const int tid = threadIdx.x;
    const int row = tid >> 2;       // 0..63
    const int lane4 = tid & 3;      // 0..3
    const int qt = blockIdx.x;      // 0..31
    const int h = blockIdx.y;
    const int b = blockIdx.z;
    const int q0 = qt * 64;
    const int qrow = q0 + row;

    const size_t bh = (size_t)(b * H_ + h) * T_;

    float qreg[16];
    {
        const float* Qp = g_Q + (bh + qrow) * D_ + lane4 * 16;
        #pragma unroll
        for (int i = 0; i < 4; i++) {
            float4 v = *(const float4*)(Qp + i * 4);
            qreg[i * 4 + 0] = v.x; qreg[i * 4 + 1] = v.y;
            qreg[i * 4 + 2] = v.z; qreg[i * 4 + 3] = v.w;
        }
    }

    const int P = spl[b];
    float acc[16];
    #pragma unroll
    for (int i = 0; i < 16; i++) acc[i] = 0.f;
    float l = 0.f;

    const float scale = 0.125f;          // 1/sqrt(64)
    const int lr = tid >> 2;             // tile-load row 0..63
    const int ls = (tid & 3) * 16;       // tile-load col base

    for (int kt = 0; kt < T_ / 64; kt++) {
        const int k0 = kt * 64;
        // tile relevant if it intersects prefix [0,P) or window [q0-WIN, q0+63]
        const bool tile_valid = (k0 < P) ||
            ((k0 <= q0 + 63) && (k0 + 63 >= q0 - WIN_));
        if (!tile_valid) continue;   // uniform across block

        const float* Kp = g_K + (bh + k0 + lr) * D_ + ls;
        const float* Vp = g_V + (bh + k0 + lr) * D_ + ls;
        __syncthreads();
        #pragma unroll
        for (int i = 0; i < 4; i++) {
            *(float4*)(&Ksm[lr][ls + i * 4]) = *(const float4*)(Kp + i * 4);
            *(float4*)(&Vsm[lr][ls + i * 4]) = *(const float4*)(Vp + i * 4);
        }
        __syncthreads();

        #pragma unroll 2
        for (int kk = 0; kk < 64; kk++) {
            float s = 0.f;
            #pragma unroll
            for (int i = 0; i < 16; i++)
                s = fmaf(qreg[i], Ksm[kk][lane4 * 16 + i], s);
            s += __shfl_xor_sync(0xffffffffu, s, 1);
            s += __shfl_xor_sync(0xffffffffu, s, 2);

            const int kg = k0 + kk;
            s *= scale;
            s = 30.0f * tanhf(s * (1.0f / 30.0f));   // softcap

            const bool valid = ((kg <= qrow) && (qrow - kg <= WIN_)) || (kg < P);
            const float p = valid ? __expf(s - 30.0f) : 0.0f;
            l += p;
            #pragma unroll
            for (int i = 0; i < 16; i++)
                acc[i] = fmaf(p, Vsm[kk][lane4 * 16 + i], acc[i]);
        }
    }

    const float inv = 1.0f / l;   // every row has >=1 valid key (k == q)
    float* outp = g_att + ((size_t)(b * T_ + qrow)) * C_ + h * D_ + lane4 * 16;
    #pragma unroll
    for (int i = 0; i < 4; i++) {
        float4 v;
        v.x = acc[i * 4 + 0] * inv; v.y = acc[i * 4 + 1] * inv;
        v.z = acc[i * 4 + 2] * inv; v.w = acc[i * 4 + 3] * inv;
        *(float4*)(outp + i * 4) = v;
    }
}

// ---------------------------------------------------------------------------
extern "C" void kernel_launch(void* const* d_in, const int* in_sizes, int n_in,
                              void* d_out, int out_size)
{
    (void)in_sizes; (void)n_in; (void)out_size;
    const float* x    = (const float*)d_in[0];
    const int*   spl  = (const int*)  d_in[1];
    const float* Wqkv = (const float*)d_in[2];
    const float* bqkv = (const float*)d_in[3];
    const float* Wprj = (const float*)d_in[4];
    const float* bprj = (const float*)d_in[5];
    float* out = (float*)d_out;

    const int M = B_ * T_;   // 4096

    // 1) fused QKV projection -> g_Q/g_K/g_V
    sgemm_kernel<0><<<dim3((3 * C_) / 128, M / 128), 256>>>(
        x, Wqkv, bqkv, nullptr, M, 3 * C_, C_);

    // 2) attention -> g_att ([B,T,C])
    attn_kernel<<<dim3(T_ / 64, H_, B_), 256>>>(spl);

    // 3) output projection -> d_out
    sgemm_kernel<1><<<dim3(C_ / 128, M / 128), 256>>>(
        nullptr, Wprj, bprj, out, M, C_, C_);
}

// round 2
// speedup vs baseline: 2.1341x; 2.1341x over previous
#include <cuda_runtime.h>
#include <math.h>

// Problem constants
#define B_ 2
#define T_ 2048
#define C_ 1024
#define H_ 16
#define D_ 64
#define WIN_ 512
#define PS_ 68   // padded Ps row stride (floats), %4==0 for float4 alignment

// Scratch (allocation-free: __device__ globals)
__device__ float g_Q[B_*H_*T_*D_];
__device__ float g_K[B_*H_*T_*D_];
__device__ float g_V[B_*H_*T_*D_];
__device__ float g_att[B_*T_*C_];

// ---------------------------------------------------------------------------
// SGEMM: C[m,n] = sum_k A[m,k] * W[n,k] + bias[n]
// MODE 0: A = x, W = W_qkv, scatter into g_Q/g_K/g_V ([B,H,T,d] layout)
// MODE 1: A = g_att (device global), W = W_proj, write d_out + bias
// 128x128 tile, BK=8, 256 threads, 8x8 micro-tile, double-buffered smem,
// single __syncthreads per K-step.
// ---------------------------------------------------------------------------
template <int MODE>
__global__ __launch_bounds__(256, 2) void sgemm_kernel(
    const float* __restrict__ A, const float* __restrict__ W,
    const float* __restrict__ bias, float* __restrict__ Cout,
    int M, int N, int K)
{
    __shared__ float As[2][8][128];
    __shared__ float Bs[2][8][128];

    const int tid = threadIdx.x;
    const int tx = tid & 15;        // n dir
    const int ty = tid >> 4;        // m dir
    const int bm = blockIdx.y;
    const int bn = blockIdx.x;

    const float* Ap = (MODE == 1) ? g_att : A;
    const float* aptr = Ap + (size_t)(bm * 128 + (tid >> 1)) * K + (tid & 1) * 4;
    const float* wptr = W  + (size_t)(bn * 128 + (tid >> 1)) * K + (tid & 1) * 4;
    const int lrow = tid >> 1;
    const int lcol = (tid & 1) * 4;

    float4 a = *(const float4*)aptr;
    float4 w = *(const float4*)wptr;
    As[0][lcol + 0][lrow] = a.x; As[0][lcol + 1][lrow] = a.y;
    As[0][lcol + 2][lrow] = a.z; As[0][lcol + 3][lrow] = a.w;
    Bs[0][lcol + 0][lrow] = w.x; Bs[0][lcol + 1][lrow] = w.y;
    Bs[0][lcol + 2][lrow] = w.z; Bs[0][lcol + 3][lrow] = w.w;

    float acc[8][8];
    #pragma unroll
    for (int i = 0; i < 8; i++)
        #pragma unroll
        for (int j = 0; j < 8; j++) acc[i][j] = 0.f;

    const int nt = K / 8;
    for (int it = 0; it < nt; ++it) {
        __syncthreads();
        const int cur = it & 1;
        if (it + 1 < nt) {
            a = *(const float4*)(aptr + (it + 1) * 8);
            w = *(const float4*)(wptr + (it + 1) * 8);
        }
        #pragma unroll
        for (int k = 0; k < 8; k++) {
            float4 ra0 = *(const float4*)&As[cur][k][ty * 8];
            float4 ra1 = *(const float4*)&As[cur][k][ty * 8 + 4];
            float4 rb0 = *(const float4*)&Bs[cur][k][tx * 8];
            float4 rb1 = *(const float4*)&Bs[cur][k][tx * 8 + 4];
            float ra[8] = {ra0.x, ra0.y, ra0.z, ra0.w, ra1.x, ra1.y, ra1.z, ra1.w};
            float rb[8] = {rb0.x, rb0.y, rb0.z, rb0.w, rb1.x, rb1.y, rb1.z, rb1.w};
            #pragma unroll
            for (int i = 0; i < 8; i++)
                #pragma unroll
                for (int j = 0; j < 8; j++)
                    acc[i][j] = fmaf(ra[i], rb[j], acc[i][j]);
        }
        if (it + 1 < nt) {
            const int nxt = cur ^ 1;
            As[nxt][lcol + 0][lrow] = a.x; As[nxt][lcol + 1][lrow] = a.y;
            As[nxt][lcol + 2][lrow] = a.z; As[nxt][lcol + 3][lrow] = a.w;
            Bs[nxt][lcol + 0][lrow] = w.x; Bs[nxt][lcol + 1][lrow] = w.y;
            Bs[nxt][lcol + 2][lrow] = w.z; Bs[nxt][lcol + 3][lrow] = w.w;
        }
    }

    // Epilogue
    #pragma unroll
    for (int i = 0; i < 8; i++) {
        const int m = bm * 128 + ty * 8 + i;
        #pragma unroll
        for (int j = 0; j < 8; j++) {
            const int n = bn * 128 + tx * 8 + j;
            float v = acc[i][j] + bias[n];
            if (MODE == 0) {
                const int sel = n >> 10;
                const int r = n & 1023;
                const int h = r >> 6;
                const int dd = r & 63;
                const int b = m >> 11;
                const int t = m & 2047;
                float* dst = (sel == 0) ? g_Q : ((sel == 1) ? g_K : g_V);
                dst[(((size_t)(b * H_ + h)) * T_ + t) * D_ + dd] = v;
            } else {
                Cout[(size_t)m * N + n] = v;
            }
        }
    }
}

// ---------------------------------------------------------------------------
// Attention, GEMM-style: 128 q-rows per block, 64-key tiles.
// QK^T and PV are both smem GEMMs; scores staged through smem (Ps).
// Softcap bounds scores to (-30,30) -> fixed softmax max of 30 (no rescale):
//   p = exp(30*tanh(s/30) - 30) = exp(-60/(E+1)),  E = exp(s/15)
// Thread layout: 256 threads = 16(ty: 8 q-rows each) x 16(tx: 4 cols each).
// ---------------------------------------------------------------------------
__global__ __launch_bounds__(256, 2) void attn_kernel(const int* __restrict__ spl)
{
    extern __shared__ float sm[];
    float* Qs = sm;                    // [64][128]  Qs[d*128 + q]  (transposed)
    float* Ks = Qs + 64 * 128;         // [64][64]   Ks[d*64 + k]   (transposed)
    float* Vs = Ks + 64 * 64;          // [64][64]   Vs[k*64 + d]   (natural)
    float* Ps = Vs + 64 * 64;          // [128][PS_]

    const int tid = threadIdx.x;
    const int tx = tid & 15;
    const int ty = tid >> 4;
    const int q0 = blockIdx.x * 128;
    const int h = blockIdx.y;
    const int b = blockIdx.z;
    const size_t bh = (size_t)(b * H_ + h) * T_;
    const int P = spl[b];

    // Load Q tile transposed: 128 rows x 64 dims = 2048 float4
    for (int i = tid; i < 2048; i += 256) {
        const int r = i & 127;
        const int c4 = i >> 7;
        float4 v = *(const float4*)(g_Q + (bh + q0 + r) * D_ + c4 * 4);
        Qs[(c4 * 4 + 0) * 128 + r] = v.x;
        Qs[(c4 * 4 + 1) * 128 + r] = v.y;
        Qs[(c4 * 4 + 2) * 128 + r] = v.z;
        Qs[(c4 * 4 + 3) * 128 + r] = v.w;
    }

    float acc[8][4];
    float lsum[8];
    #pragma unroll
    for (int i = 0; i < 8; i++) {
        lsum[i] = 0.f;
        #pragma unroll
        for (int j = 0; j < 4; j++) acc[i][j] = 0.f;
    }

    const float scale = 0.125f;   // 1/sqrt(64)

    for (int kt = 0; kt < T_ / 64; kt++) {
        const int k0 = kt * 64;
        // tile relevant if it intersects prefix [0,P) or window band
        const bool tv = (k0 < P) ||
            ((k0 <= q0 + 127) && (k0 + 63 >= q0 - WIN_));
        if (!tv) continue;   // uniform across block

        __syncthreads();   // prior PV reads of Ks/Vs/Ps done
        // K transposed
        for (int i = tid; i < 1024; i += 256) {
            const int r = i & 63;
            const int c4 = i >> 6;
            float4 kv = *(const float4*)(g_K + (bh + k0 + r) * D_ + c4 * 4);
            Ks[(c4 * 4 + 0) * 64 + r] = kv.x;
            Ks[(c4 * 4 + 1) * 64 + r] = kv.y;
            Ks[(c4 * 4 + 2) * 64 + r] = kv.z;
            Ks[(c4 * 4 + 3) * 64 + r] = kv.w;
        }
        // V natural
        for (int i = tid; i < 1024; i += 256) {
            const int r = i >> 4;
            const int c4 = i & 15;
            *(float4*)(Vs + r * 64 + c4 * 4) =
                *(const float4*)(g_V + (bh + k0 + r) * D_ + c4 * 4);
        }
        __syncthreads();

        // ---- QK^T: s[8][4] ----
        float s[8][4];
        #pragma unroll
        for (int i = 0; i < 8; i++)
            #pragma unroll
            for (int j = 0; j < 4; j++) s[i][j] = 0.f;

        #pragma unroll 4
        for (int kd = 0; kd < 64; kd++) {
            float4 a0 = *(const float4*)(Qs + kd * 128 + ty * 8);
            float4 a1 = *(const float4*)(Qs + kd * 128 + ty * 8 + 4);
            float4 bb = *(const float4*)(Ks + kd * 64 + tx * 4);
            float ra[8] = {a0.x, a0.y, a0.z, a0.w, a1.x, a1.y, a1.z, a1.w};
            float rb[4] = {bb.x, bb.y, bb.z, bb.w};
            #pragma unroll
            for (int i = 0; i < 8; i++)
                #pragma unroll
                for (int j = 0; j < 4; j++)
                    s[i][j] = fmaf(ra[i], rb[j], s[i][j]);
        }

        // ---- softcap + mask + exp -> Ps ----
        #pragma unroll
        for (int i = 0; i < 8; i++) {
            const int qrow = q0 + ty * 8 + i;
            float pv[4];
            #pragma unroll
            for (int j = 0; j < 4; j++) {
                const int kg = k0 + tx * 4 + j;
                const float sc = s[i][j] * scale;
                // p = exp(30*tanh(sc/30) - 30) = exp(-60/(E+1)), E = exp(sc/15)
                const float E = __expf(sc * (1.0f / 15.0f));
                float p = __expf(__fdividef(-60.0f, E + 1.0f));
                const bool valid = ((kg <= qrow) && (qrow - kg <= WIN_)) || (kg < P);
                p = valid ? p : 0.0f;
                pv[j] = p;
                lsum[i] += p;
            }
            float4 pq = {pv[0], pv[1], pv[2], pv[3]};
            *(float4*)(Ps + (ty * 8 + i) * PS_ + tx * 4) = pq;
        }
        __syncthreads();

        // ---- PV: acc += P @ V, chunked 4 keys at a time ----
        #pragma unroll 2
        for (int kk = 0; kk < 64; kk += 4) {
            float pr[8][4];
            #pragma unroll
            for (int i = 0; i < 8; i++) {
                float4 t = *(const float4*)(Ps + (ty * 8 + i) * PS_ + kk);
                pr[i][0] = t.x; pr[i][1] = t.y; pr[i][2] = t.z; pr[i][3] = t.w;
            }
            #pragma unroll
            for (int c = 0; c < 4; c++) {
                float4 vv = *(const float4*)(Vs + (kk + c) * 64 + tx * 4);
                #pragma unroll
                for (int i = 0; i < 8; i++) {
                    acc[i][0] = fmaf(pr[i][c], vv.x, acc[i][0]);
                    acc[i][1] = fmaf(pr[i][c], vv.y, acc[i][1]);
                    acc[i][2] = fmaf(pr[i][c], vv.z, acc[i][2]);
                    acc[i][3] = fmaf(pr[i][c], vv.w, acc[i][3]);
                }
            }
        }
    }

    // ---- row-sum reduction across tx (lane bits 0..3), normalize, write ----
    #pragma unroll
    for (int i = 0; i < 8; i++) {
        float v = lsum[i];
        v += __shfl_xor_sync(0xffffffffu, v, 1);
        v += __shfl_xor_sync(0xffffffffu, v, 2);
        v += __shfl_xor_sync(0xffffffffu, v, 4);
        v += __shfl_xor_sync(0xffffffffu, v, 8);
        const float inv = 1.0f / v;   // every q-row has >=1 valid key (k==q)
        float4 o;
        o.x = acc[i][0] * inv; o.y = acc[i][1] * inv;
        o.z = acc[i][2] * inv; o.w = acc[i][3] * inv;
        *(float4*)(g_att + ((size_t)(b * T_ + q0 + ty * 8 + i)) * C_
                   + h * D_ + tx * 4) = o;
    }
}

// ---------------------------------------------------------------------------
extern "C" void kernel_launch(void* const* d_in, const int* in_sizes, int n_in,
                              void* d_out, int out_size)
{
    (void)in_sizes; (void)n_in; (void)out_size;
    const float* x    = (const float*)d_in[0];
    const int*   spl  = (const int*)  d_in[1];
    const float* Wqkv = (const float*)d_in[2];
    const float* bqkv = (const float*)d_in[3];
    const float* Wprj = (const float*)d_in[4];
    const float* bprj = (const float*)d_in[5];
    float* out = (float*)d_out;

    const int M = B_ * T_;   // 4096
    const int attn_smem = (64 * 128 + 64 * 64 + 64 * 64 + 128 * PS_) * 4; // 100352B
    static_assert((64 * 128 + 64 * 64 + 64 * 64 + 128 * PS_) * 4 == 100352, "");
    cudaFuncSetAttribute(attn_kernel,
                         cudaFuncAttributeMaxDynamicSharedMemorySize, attn_smem);

    // 1) fused QKV projection -> g_Q/g_K/g_V
    sgemm_kernel<0><<<dim3((3 * C_) / 128, M / 128), 256>>>(
        x, Wqkv, bqkv, nullptr, M, 3 * C_, C_);

    // 2) attention -> g_att ([B,T,C])
    attn_kernel<<<dim3(T_ / 128, H_, B_), 256, attn_smem>>>(spl);

    // 3) output projection -> d_out
    sgemm_kernel<1><<<dim3(C_ / 128, M / 128), 256>>>(
        nullptr, Wprj, bprj, out, M, C_, C_);
}

// round 4
// speedup vs baseline: 3.8571x; 1.8073x over previous
#include <cuda_runtime.h>
#include <cuda_bf16.h>
#include <math.h>
#include <stdint.h>

// Problem constants
#define B_ 2
#define T_ 2048
#define C_ 1024
#define H_ 16
#define D_ 64
#define WIN_ 512
#define PS_ 68
#define K_ 1024

// GEMM tiling
#define BK 32
#define SP 40                       // padded smem row stride (bf16 elems)
#define TILE_B (128 * SP * 2)       // bytes per 128xBK tile (10240)
#define BUF_B (4 * TILE_B)          // 4 tiles (Ah, Al, Wh, Wl) = 40960
#define GSMEM (2 * BUF_B)           // double buffered = 81920

// ---------------- scratch (allocation-free) ----------------
__device__ float g_Q[B_*H_*T_*D_];
__device__ float g_K[B_*H_*T_*D_];
__device__ float g_V[B_*H_*T_*D_];
__device__ __nv_bfloat16 g_xh[B_*T_*C_],  g_xl[B_*T_*C_];
__device__ __nv_bfloat16 g_wqh[3*C_*C_],  g_wql[3*C_*C_];
__device__ __nv_bfloat16 g_wph[C_*C_],    g_wpl[C_*C_];
__device__ __nv_bfloat16 g_ah[B_*T_*C_],  g_al[B_*T_*C_];

__device__ __forceinline__ uint32_t smem_u32(const void* p) {
    uint32_t a;
    asm("{ .reg .u64 t; cvta.to.shared.u64 t, %1; cvt.u32.u64 %0, t; }"
        : "=r"(a) : "l"(p));
    return a;
}
#define LDMX4(r0, r1, r2, r3, addr)                                          \
    asm volatile("ldmatrix.sync.aligned.m8n8.x4.shared.b16 {%0,%1,%2,%3}, [%4];" \
        : "=r"(r0), "=r"(r1), "=r"(r2), "=r"(r3) : "r"(addr))
#define MMA16816(c, a0, a1, a2, a3, b0, b1)                                  \
    asm volatile("mma.sync.aligned.m16n8k16.row.col.f32.bf16.bf16.f32 "      \
        "{%0,%1,%2,%3}, {%4,%5,%6,%7}, {%8,%9}, {%0,%1,%2,%3};"              \
        : "+f"((c)[0]), "+f"((c)[1]), "+f"((c)[2]), "+f"((c)[3])             \
        : "r"(a0), "r"(a1), "r"(a2), "r"(a3), "r"(b0), "r"(b1))

// ---------------- split fp32 -> bf16 hi/lo ----------------
__global__ __launch_bounds__(256) void split_kernel(
    const float* __restrict__ s, __nv_bfloat16* __restrict__ hi,
    __nv_bfloat16* __restrict__ lo, int n4)
{
    int i = blockIdx.x * 256 + threadIdx.x;
    if (i >= n4) return;
    float4 v = ((const float4*)s)[i];
    __nv_bfloat16 h0 = __float2bfloat16(v.x), h1 = __float2bfloat16(v.y);
    __nv_bfloat16 h2 = __float2bfloat16(v.z), h3 = __float2bfloat16(v.w);
    __nv_bfloat16 l0 = __float2bfloat16(v.x - __bfloat162float(h0));
    __nv_bfloat16 l1 = __float2bfloat16(v.y - __bfloat162float(h1));
    __nv_bfloat16 l2 = __float2bfloat16(v.z - __bfloat162float(h2));
    __nv_bfloat16 l3 = __float2bfloat16(v.w - __bfloat162float(h3));
    ((__nv_bfloat162*)hi)[2*i]   = __nv_bfloat162(h0, h1);
    ((__nv_bfloat162*)hi)[2*i+1] = __nv_bfloat162(h2, h3);
    ((__nv_bfloat162*)lo)[2*i]   = __nv_bfloat162(l0, l1);
    ((__nv_bfloat162*)lo)[2*i+1] = __nv_bfloat162(l2, l3);
}

// ---------------- bf16-split tensor-core GEMM (HMMA via mma.sync) --------
// D[m,n] = sum_k A[m,k]*W[n,k] + bias[n] ~= Ah*Wh + Ah*Wl + Al*Wh.
// CTA: 128x128, BK=32, 512 threads = 16 warps (4x4), warp tile 32x32.
// MODE 0: scatter into g_Q/g_K/g_V.  MODE 1: row-major out [M][C_].
template <int MODE>
__global__ __launch_bounds__(512) void gemm_bf16_kernel(
    const __nv_bfloat16* __restrict__ Ahi, const __nv_bfloat16* __restrict__ Alo,
    const __nv_bfloat16* __restrict__ Bhi, const __nv_bfloat16* __restrict__ Blo,
    const float* __restrict__ bias, float* __restrict__ Cout)
{
    extern __shared__ char smem[];
    const uint32_t sb = smem_u32(smem);
    const int tid = threadIdx.x;
    const int wid = tid >> 5;
    const int lane = tid & 31;
    const int warp_m = wid >> 2;     // 0..3
    const int warp_n = wid & 3;      // 0..3
    const int bn = blockIdx.x, bm = blockIdx.y;

    // gmem load mapping: thread -> (row, 8-elem chunk) of a 128xBK tile
    const int grow = tid >> 2;       // 0..127
    const int gc8  = tid & 3;        // 0..3 (x8 bf16)
    const __nv_bfloat16* srcs[4] = {
        Ahi + (size_t)(bm * 128 + grow) * K_ + gc8 * 8,
        Alo + (size_t)(bm * 128 + grow) * K_ + gc8 * 8,
        Bhi + (size_t)(bn * 128 + grow) * K_ + gc8 * 8,
        Blo + (size_t)(bn * 128 + grow) * K_ + gc8 * 8 };
    const uint32_t soff = (uint32_t)(grow * SP + gc8 * 8) * 2;

    // ldmatrix per-lane offsets (bytes, within a tile)
    const int a_m = warp_m * 32 + (lane & 7) + ((lane >> 3) & 1) * 8;
    const int a_k = (lane >> 4) * 8;
    const uint32_t aoff = (uint32_t)(a_m * SP + a_k) * 2;
    const int b_n = warp_n * 32 + (lane & 7) + (lane >> 4) * 8;
    const int b_k = ((lane >> 3) & 1) * 8;
    const uint32_t boff = (uint32_t)(b_n * SP + b_k) * 2;

    float acc[2][4][4];
    #pragma unroll
    for (int i = 0; i < 2; i++)
        #pragma unroll
        for (int j = 0; j < 4; j++)
            #pragma unroll
            for (int c = 0; c < 4; c++) acc[i][j][c] = 0.f;

    const int NT = K_ / BK;   // 32
    uint4 pv[4];
    #pragma unroll
    for (int t = 0; t < 4; t++) pv[t] = *(const uint4*)(srcs[t]);
    #pragma unroll
    for (int t = 0; t < 4; t++)
        *(uint4*)(smem + t * TILE_B + soff) = pv[t];

    for (int it = 0; it < NT; ++it) {
        __syncthreads();
        const uint32_t tb = sb + (uint32_t)(it & 1) * BUF_B;
        if (it + 1 < NT) {
            #pragma unroll
            for (int t = 0; t < 4; t++)
                pv[t] = *(const uint4*)(srcs[t] + (it + 1) * BK);
        }

        #pragma unroll
        for (int kk = 0; kk < BK; kk += 16) {
            uint32_t ah[2][4], al[2][4], bh[2][4], bl[2][4];
            #pragma unroll
            for (int mf = 0; mf < 2; mf++) {
                const uint32_t ao = tb + aoff + (uint32_t)(mf * 16 * SP + kk) * 2;
                LDMX4(ah[mf][0], ah[mf][1], ah[mf][2], ah[mf][3], ao);
                LDMX4(al[mf][0], al[mf][1], al[mf][2], al[mf][3], ao + TILE_B);
            }
            #pragma unroll
            for (int nf2 = 0; nf2 < 2; nf2++) {
                const uint32_t bo = tb + 2 * TILE_B + boff
                                  + (uint32_t)(nf2 * 16 * SP + kk) * 2;
                LDMX4(bh[nf2][0], bh[nf2][1], bh[nf2][2], bh[nf2][3], bo);
                LDMX4(bl[nf2][0], bl[nf2][1], bl[nf2][2], bl[nf2][3], bo + TILE_B);
            }
            #pragma unroll
            for (int mf = 0; mf < 2; mf++)
                #pragma unroll
                for (int nf = 0; nf < 4; nf++) {
                    const int n2 = nf >> 1, hh = (nf & 1) * 2;
                    MMA16816(acc[mf][nf], ah[mf][0], ah[mf][1], ah[mf][2], ah[mf][3],
                             bh[n2][hh], bh[n2][hh + 1]);
                    MMA16816(acc[mf][nf], ah[mf][0], ah[mf][1], ah[mf][2], ah[mf][3],
                             bl[n2][hh], bl[n2][hh + 1]);
                    MMA16816(acc[mf][nf], al[mf][0], al[mf][1], al[mf][2], al[mf][3],
                             bh[n2][hh], bh[n2][hh + 1]);
                }
        }

        if (it + 1 < NT) {
            char* db = smem + ((it + 1) & 1) * BUF_B;
            #pragma unroll
            for (int t = 0; t < 4; t++)
                *(uint4*)(db + t * TILE_B + soff) = pv[t];
        }
    }
    __syncthreads();

    // stage through smem for coalesced writes: Ep[128][129]
    float* Ep = (float*)smem;
    const int g = lane >> 2, tg = lane & 3;
    #pragma unroll
    for (int mf = 0; mf < 2; mf++)
        #pragma unroll
        for (int nf = 0; nf < 4; nf++) {
            const int r0 = warp_m * 32 + mf * 16 + g;
            const int c0 = warp_n * 32 + nf * 8 + tg * 2;
            Ep[r0 * 129 + c0]       = acc[mf][nf][0];
            Ep[r0 * 129 + c0 + 1]   = acc[mf][nf][1];
            Ep[(r0 + 8) * 129 + c0]     = acc[mf][nf][2];
            Ep[(r0 + 8) * 129 + c0 + 1] = acc[mf][nf][3];
        }
    __syncthreads();

    const int col = tid & 127;
    const int rg = tid >> 7;         // 0..3
    const float biasv = bias[bn * 128 + col];
    if (MODE == 0) {
        const int sel = bn >> 3;
        const int h = ((bn & 7) << 1) + (col >> 6);
        const int dd = col & 63;
        float* dst = (sel == 0) ? g_Q : ((sel == 1) ? g_K : g_V);
        #pragma unroll 4
        for (int r = 0; r < 32; r++) {
            const int row = rg * 32 + r;
            const int m = bm * 128 + row;
            const int b = m >> 11, t = m & 2047;
            dst[(((size_t)(b * H_ + h)) * T_ + t) * D_ + dd] =
                Ep[row * 129 + col] + biasv;
        }
    } else {
        #pragma unroll 4
        for (int r = 0; r < 32; r++) {
            const int row = rg * 32 + r;
            const int m = bm * 128 + row;
            Cout[(size_t)m * C_ + bn * 128 + col] = Ep[row * 129 + col] + biasv;
        }
    }
}

// ---------------------------------------------------------------------------
// Attention (fp32): 128 q-rows/block, 64-key tiles.
// p = exp(30*tanh(s/30) - 30) = exp(-60/(E+1)), E = exp(s/15); fixed max.
// Epilogue emits bf16 hi/lo for the proj GEMM.
// ---------------------------------------------------------------------------
__global__ __launch_bounds__(256, 2) void attn_kernel(const int* __restrict__ spl)
{
    extern __shared__ float sm[];
    float* Qs = sm;                    // [64][128] transposed
    float* Ks = Qs + 64 * 128;         // [64][64]  transposed
    float* Vs = Ks + 64 * 64;          // [64][64]  natural
    float* Ps = Vs + 64 * 64;          // [128][PS_]

    const int tid = threadIdx.x;
    const int tx = tid & 15;
    const int ty = tid >> 4;
    const int q0 = blockIdx.x * 128;
    const int h = blockIdx.y;
    const int b = blockIdx.z;
    const size_t bh = (size_t)(b * H_ + h) * T_;
    const int P = spl[b];

    for (int i = tid; i < 2048; i += 256) {
        const int r = i & 127;
        const int c4 = i >> 7;
        float4 v = *(const float4*)(g_Q + (bh + q0 + r) * D_ + c4 * 4);
        Qs[(c4 * 4 + 0) * 128 + r] = v.x;
        Qs[(c4 * 4 + 1) * 128 + r] = v.y;
        Qs[(c4 * 4 + 2) * 128 + r] = v.z;
        Qs[(c4 * 4 + 3) * 128 + r] = v.w;
    }

    float acc[8][4];
    float lsum[8];
    #pragma unroll
    for (int i = 0; i < 8; i++) {
        lsum[i] = 0.f;
        #pragma unroll
        for (int j = 0; j < 4; j++) acc[i][j] = 0.f;
    }
    const float scale = 0.125f;

    for (int kt = 0; kt < T_ / 64; kt++) {
        const int k0 = kt * 64;
        const bool tv = (k0 < P) || ((k0 <= q0 + 127) && (k0 + 63 >= q0 - WIN_));
        if (!tv) continue;

        __syncthreads();
        for (int i = tid; i < 1024; i += 256) {
            const int r = i & 63;
            const int c4 = i >> 6;
            float4 kv = *(const float4*)(g_K + (bh + k0 + r) * D_ + c4 * 4);
            Ks[(c4 * 4 + 0) * 64 + r] = kv.x;
            Ks[(c4 * 4 + 1) * 64 + r] = kv.y;
            Ks[(c4 * 4 + 2) * 64 + r] = kv.z;
            Ks[(c4 * 4 + 3) * 64 + r] = kv.w;
        }
        for (int i = tid; i < 1024; i += 256) {
            const int r = i >> 4;
            const int c4 = i & 15;
            *(float4*)(Vs + r * 64 + c4 * 4) =
                *(const float4*)(g_V + (bh + k0 + r) * D_ + c4 * 4);
        }
        __syncthreads();

        float s[8][4];
        #pragma unroll
        for (int i = 0; i < 8; i++)
            #pragma unroll
            for (int j = 0; j < 4; j++) s[i][j] = 0.f;

        #pragma unroll 4
        for (int kd = 0; kd < 64; kd++) {
            float4 a0 = *(const float4*)(Qs + kd * 128 + ty * 8);
            float4 a1 = *(const float4*)(Qs + kd * 128 + ty * 8 + 4);
            float4 bb = *(const float4*)(Ks + kd * 64 + tx * 4);
            float ra[8] = {a0.x, a0.y, a0.z, a0.w, a1.x, a1.y, a1.z, a1.w};
            float rb[4] = {bb.x, bb.y, bb.z, bb.w};
            #pragma unroll
            for (int i = 0; i < 8; i++)
                #pragma unroll
                for (int j = 0; j < 4; j++)
                    s[i][j] = fmaf(ra[i], rb[j], s[i][j]);
        }

        #pragma unroll
        for (int i = 0; i < 8; i++) {
            const int qrow = q0 + ty * 8 + i;
            float pvv[4];
            #pragma unroll
            for (int j = 0; j < 4; j++) {
                const int kg = k0 + tx * 4 + j;
                const float sc = s[i][j] * scale;
                const float E = __expf(sc * (1.0f / 15.0f));
                float p = __expf(__fdividef(-60.0f, E + 1.0f));
                const bool valid = ((kg <= qrow) && (qrow - kg <= WIN_)) || (kg < P);
                p = valid ? p : 0.0f;
                pvv[j] = p;
                lsum[i] += p;
            }
            float4 pq = {pvv[0], pvv[1], pvv[2], pvv[3]};
            *(float4*)(Ps + (ty * 8 + i) * PS_ + tx * 4) = pq;
        }
        __syncthreads();

        #pragma unroll 2
        for (int kk = 0; kk < 64; kk += 4) {
            float pr[8][4];
            #pragma unroll
            for (int i = 0; i < 8; i++) {
                float4 t = *(const float4*)(Ps + (ty * 8 + i) * PS_ + kk);
                pr[i][0] = t.x; pr[i][1] = t.y; pr[i][2] = t.z; pr[i][3] = t.w;
            }
            #pragma unroll
            for (int c = 0; c < 4; c++) {
                float4 vv = *(const float4*)(Vs + (kk + c) * 64 + tx * 4);
                #pragma unroll
                for (int i = 0; i < 8; i++) {
                    acc[i][0] = fmaf(pr[i][c], vv.x, acc[i][0]);
                    acc[i][1] = fmaf(pr[i][c], vv.y, acc[i][1]);
                    acc[i][2] = fmaf(pr[i][c], vv.z, acc[i][2]);
                    acc[i][3] = fmaf(pr[i][c], vv.w, acc[i][3]);
                }
            }
        }
    }

    #pragma unroll
    for (int i = 0; i < 8; i++) {
        float v = lsum[i];
        v += __shfl_xor_sync(0xffffffffu, v, 1);
        v += __shfl_xor_sync(0xffffffffu, v, 2);
        v += __shfl_xor_sync(0xffffffffu, v, 4);
        v += __shfl_xor_sync(0xffffffffu, v, 8);
        const float inv = 1.0f / v;
        float o[4];
        #pragma unroll
        for (int j = 0; j < 4; j++) o[j] = acc[i][j] * inv;
        const size_t idx = ((size_t)(b * T_ + q0 + ty * 8 + i)) * C_ + h * D_ + tx * 4;
        __nv_bfloat16 hs[4], ls[4];
        #pragma unroll
        for (int j = 0; j < 4; j++) {
            hs[j] = __float2bfloat16(o[j]);
            ls[j] = __float2bfloat16(o[j] - __bfloat162float(hs[j]));
        }
        *((__nv_bfloat162*)(g_ah + idx))     = __nv_bfloat162(hs[0], hs[1]);
        *((__nv_bfloat162*)(g_ah + idx + 2)) = __nv_bfloat162(hs[2], hs[3]);
        *((__nv_bfloat162*)(g_al + idx))     = __nv_bfloat162(ls[0], ls[1]);
        *((__nv_bfloat162*)(g_al + idx + 2)) = __nv_bfloat162(ls[2], ls[3]);
    }
}

// ---------------------------------------------------------------------------
extern "C" void kernel_launch(void* const* d_in, const int* in_sizes, int n_in,
                              void* d_out, int out_size)
{
    (void)in_sizes; (void)n_in; (void)out_size;
    const float* x    = (const float*)d_in[0];
    const int*   spl  = (const int*)  d_in[1];
    const float* Wqkv = (const float*)d_in[2];
    const float* bqkv = (const float*)d_in[3];
    const float* Wprj = (const float*)d_in[4];
    const float* bprj = (const float*)d_in[5];
    float* out = (float*)d_out;

    const int attn_smem = (64 * 128 + 64 * 64 + 64 * 64 + 128 * PS_) * 4;
    cudaFuncSetAttribute(attn_kernel,
                         cudaFuncAttributeMaxDynamicSharedMemorySize, attn_smem);
    cudaFuncSetAttribute(gemm_bf16_kernel<0>,
                         cudaFuncAttributeMaxDynamicSharedMemorySize, GSMEM);
    cudaFuncSetAttribute(gemm_bf16_kernel<1>,
                         cudaFuncAttributeMaxDynamicSharedMemorySize, GSMEM);

    __nv_bfloat16 *xh, *xl, *wqh, *wql, *wph, *wpl, *ah, *al;
    cudaGetSymbolAddress((void**)&xh,  g_xh);  cudaGetSymbolAddress((void**)&xl,  g_xl);
    cudaGetSymbolAddress((void**)&wqh, g_wqh); cudaGetSymbolAddress((void**)&wql, g_wql);
    cudaGetSymbolAddress((void**)&wph, g_wph); cudaGetSymbolAddress((void**)&wpl, g_wpl);
    cudaGetSymbolAddress((void**)&ah,  g_ah);  cudaGetSymbolAddress((void**)&al,  g_al);

    // 0) split fp32 inputs into bf16 hi/lo
    split_kernel<<<(B_*T_*C_/4 + 255)/256, 256>>>(x, xh, xl, B_*T_*C_/4);
    split_kernel<<<(3*C_*C_/4 + 255)/256, 256>>>(Wqkv, wqh, wql, 3*C_*C_/4);
    split_kernel<<<(C_*C_/4 + 255)/256, 256>>>(Wprj, wph, wpl, C_*C_/4);

    // 1) QKV projection (HMMA) -> g_Q/g_K/g_V
    gemm_bf16_kernel<0><<<dim3(3*C_/128, B_*T_/128), 512, GSMEM>>>(
        xh, xl, wqh, wql, bqkv, nullptr);

    // 2) attention -> g_ah/g_al (bf16 hi/lo)
    attn_kernel<<<dim3(T_/128, H_, B_), 256, attn_smem>>>(spl);

    // 3) output projection (HMMA) -> d_out
    gemm_bf16_kernel<1><<<dim3(C_/128, B_*T_/128), 512, GSMEM>>>(
        ah, al, wph, wpl, bprj, out);
}

// round 5
// speedup vs baseline: 5.4123x; 1.4032x over previous
#include <cuda_runtime.h>
#include <cuda_bf16.h>
#include <math.h>
#include <stdint.h>

// Problem constants
#define B_ 2
#define T_ 2048
#define C_ 1024
#define H_ 16
#define D_ 64
#define WIN_ 512
#define K_ 1024

// GEMM tiling
#define BK 32
#define SP 40                       // padded smem row stride (bf16 elems)
#define TILE_B (128 * SP * 2)       // bytes per 128xBK tile (10240)
#define BUF_B (4 * TILE_B)          // 4 tiles (Ah, Al, Wh, Wl) = 40960
#define GSMEM (2 * BUF_B)           // double buffered = 81920

// Attention smem
#define ASP 72                      // padded row stride (bf16 elems)
#define ATTN_SMEM ((2*128 + 4*64) * ASP * 2)   // 73728 bytes

// ---------------- scratch (allocation-free) ----------------
__device__ __nv_bfloat16 g_Qh[B_*H_*T_*D_], g_Ql[B_*H_*T_*D_];
__device__ __nv_bfloat16 g_Kh[B_*H_*T_*D_], g_Kl[B_*H_*T_*D_];
__device__ __nv_bfloat16 g_Vh[B_*H_*T_*D_], g_Vl[B_*H_*T_*D_];
__device__ __nv_bfloat16 g_xh[B_*T_*C_],  g_xl[B_*T_*C_];
__device__ __nv_bfloat16 g_wqh[3*C_*C_],  g_wql[3*C_*C_];
__device__ __nv_bfloat16 g_wph[C_*C_],    g_wpl[C_*C_];
__device__ __nv_bfloat16 g_ah[B_*T_*C_],  g_al[B_*T_*C_];

__device__ __forceinline__ uint32_t smem_u32(const void* p) {
    uint32_t a;
    asm("{ .reg .u64 t; cvta.to.shared.u64 t, %1; cvt.u32.u64 %0, t; }"
        : "=r"(a) : "l"(p));
    return a;
}
#define LDMX4(r0, r1, r2, r3, addr)                                          \
    asm volatile("ldmatrix.sync.aligned.m8n8.x4.shared.b16 {%0,%1,%2,%3}, [%4];" \
        : "=r"(r0), "=r"(r1), "=r"(r2), "=r"(r3) : "r"(addr))
#define LDMX4T(r0, r1, r2, r3, addr)                                         \
    asm volatile("ldmatrix.sync.aligned.m8n8.x4.trans.shared.b16 {%0,%1,%2,%3}, [%4];" \
        : "=r"(r0), "=r"(r1), "=r"(r2), "=r"(r3) : "r"(addr))
#define MMA16816(c, a0, a1, a2, a3, b0, b1)                                  \
    asm volatile("mma.sync.aligned.m16n8k16.row.col.f32.bf16.bf16.f32 "      \
        "{%0,%1,%2,%3}, {%4,%5,%6,%7}, {%8,%9}, {%0,%1,%2,%3};"              \
        : "+f"((c)[0]), "+f"((c)[1]), "+f"((c)[2]), "+f"((c)[3])             \
        : "r"(a0), "r"(a1), "r"(a2), "r"(a3), "r"(b0), "r"(b1))
// pack two fp32 -> bf16x2 (lo = first, hi = second)
#define PACKBF2(r, lo, hi)                                                   \
    asm("cvt.rn.bf16x2.f32 %0, %1, %2;" : "=r"(r) : "f"(hi), "f"(lo))

// ---------------- split fp32 -> bf16 hi/lo ----------------
__global__ __launch_bounds__(256) void split_kernel(
    const float* __restrict__ s, __nv_bfloat16* __restrict__ hi,
    __nv_bfloat16* __restrict__ lo, int n4)
{
    int i = blockIdx.x * 256 + threadIdx.x;
    if (i >= n4) return;
    float4 v = ((const float4*)s)[i];
    __nv_bfloat16 h0 = __float2bfloat16(v.x), h1 = __float2bfloat16(v.y);
    __nv_bfloat16 h2 = __float2bfloat16(v.z), h3 = __float2bfloat16(v.w);
    __nv_bfloat16 l0 = __float2bfloat16(v.x - __bfloat162float(h0));
    __nv_bfloat16 l1 = __float2bfloat16(v.y - __bfloat162float(h1));
    __nv_bfloat16 l2 = __float2bfloat16(v.z - __bfloat162float(h2));
    __nv_bfloat16 l3 = __float2bfloat16(v.w - __bfloat162float(h3));
    ((__nv_bfloat162*)hi)[2*i]   = __nv_bfloat162(h0, h1);
    ((__nv_bfloat162*)hi)[2*i+1] = __nv_bfloat162(h2, h3);
    ((__nv_bfloat162*)lo)[2*i]   = __nv_bfloat162(l0, l1);
    ((__nv_bfloat162*)lo)[2*i+1] = __nv_bfloat162(l2, l3);
}

// ---------------- bf16-split tensor-core GEMM (HMMA) --------
// D[m,n] = sum_k A[m,k]*W[n,k] + bias[n] ~= Ah*Wh + Ah*Wl + Al*Wh.
// CTA: 128x128, BK=32, 512 threads = 16 warps (4x4), warp tile 32x32.
// MODE 0: split-scatter into g_{Q,K,V}{h,l}.  MODE 1: fp32 row-major out.
template <int MODE>
__global__ __launch_bounds__(512) void gemm_bf16_kernel(
    const __nv_bfloat16* __restrict__ Ahi, const __nv_bfloat16* __restrict__ Alo,
    const __nv_bfloat16* __restrict__ Bhi, const __nv_bfloat16* __restrict__ Blo,
    const float* __restrict__ bias, float* __restrict__ Cout)
{
    extern __shared__ char smem[];
    const uint32_t sb = smem_u32(smem);
    const int tid = threadIdx.x;
    const int wid = tid >> 5;
    const int lane = tid & 31;
    const int warp_m = wid >> 2;
    const int warp_n = wid & 3;
    const int bn = blockIdx.x, bm = blockIdx.y;

    const int grow = tid >> 2;
    const int gc8  = tid & 3;
    const __nv_bfloat16* srcs[4] = {
        Ahi + (size_t)(bm * 128 + grow) * K_ + gc8 * 8,
        Alo + (size_t)(bm * 128 + grow) * K_ + gc8 * 8,
        Bhi + (size_t)(bn * 128 + grow) * K_ + gc8 * 8,
        Blo + (size_t)(bn * 128 + grow) * K_ + gc8 * 8 };
    const uint32_t soff = (uint32_t)(grow * SP + gc8 * 8) * 2;

    const int a_m = warp_m * 32 + (lane & 7) + ((lane >> 3) & 1) * 8;
    const int a_k = (lane >> 4) * 8;
    const uint32_t aoff = (uint32_t)(a_m * SP + a_k) * 2;
    const int b_n = warp_n * 32 + (lane & 7) + (lane >> 4) * 8;
    const int b_k = ((lane >> 3) & 1) * 8;
    const uint32_t boff = (uint32_t)(b_n * SP + b_k) * 2;

    float acc[2][4][4];
    #pragma unroll
    for (int i = 0; i < 2; i++)
        #pragma unroll
        for (int j = 0; j < 4; j++)
            #pragma unroll
            for (int c = 0; c < 4; c++) acc[i][j][c] = 0.f;

    const int NT = K_ / BK;
    uint4 pv[4];
    #pragma unroll
    for (int t = 0; t < 4; t++) pv[t] = *(const uint4*)(srcs[t]);
    #pragma unroll
    for (int t = 0; t < 4; t++)
        *(uint4*)(smem + t * TILE_B + soff) = pv[t];

    for (int it = 0; it < NT; ++it) {
        __syncthreads();
        const uint32_t tb = sb + (uint32_t)(it & 1) * BUF_B;
        if (it + 1 < NT) {
            #pragma unroll
            for (int t = 0; t < 4; t++)
                pv[t] = *(const uint4*)(srcs[t] + (it + 1) * BK);
        }

        #pragma unroll
        for (int kk = 0; kk < BK; kk += 16) {
            uint32_t ah[2][4], al[2][4], bh[2][4], bl[2][4];
            #pragma unroll
            for (int mf = 0; mf < 2; mf++) {
                const uint32_t ao = tb + aoff + (uint32_t)(mf * 16 * SP + kk) * 2;
                LDMX4(ah[mf][0], ah[mf][1], ah[mf][2], ah[mf][3], ao);
                LDMX4(al[mf][0], al[mf][1], al[mf][2], al[mf][3], ao + TILE_B);
            }
            #pragma unroll
            for (int nf2 = 0; nf2 < 2; nf2++) {
                const uint32_t bo = tb + 2 * TILE_B + boff
                                  + (uint32_t)(nf2 * 16 * SP + kk) * 2;
                LDMX4(bh[nf2][0], bh[nf2][1], bh[nf2][2], bh[nf2][3], bo);
                LDMX4(bl[nf2][0], bl[nf2][1], bl[nf2][2], bl[nf2][3], bo + TILE_B);
            }
            #pragma unroll
            for (int mf = 0; mf < 2; mf++)
                #pragma unroll
                for (int nf = 0; nf < 4; nf++) {
                    const int n2 = nf >> 1, hh = (nf & 1) * 2;
                    MMA16816(acc[mf][nf], ah[mf][0], ah[mf][1], ah[mf][2], ah[mf][3],
                             bh[n2][hh], bh[n2][hh + 1]);
                    MMA16816(acc[mf][nf], ah[mf][0], ah[mf][1], ah[mf][2], ah[mf][3],
                             bl[n2][hh], bl[n2][hh + 1]);
                    MMA16816(acc[mf][nf], al[mf][0], al[mf][1], al[mf][2], al[mf][3],
                             bh[n2][hh], bh[n2][hh + 1]);
                }
        }

        if (it + 1 < NT) {
            char* db = smem + ((it + 1) & 1) * BUF_B;
            #pragma unroll
            for (int t = 0; t < 4; t++)
                *(uint4*)(db + t * TILE_B + soff) = pv[t];
        }
    }
    __syncthreads();

    // stage through smem: Ep[128][129]
    float* Ep = (float*)smem;
    const int g = lane >> 2, tg = lane & 3;
    #pragma unroll
    for (int mf = 0; mf < 2; mf++)
        #pragma unroll
        for (int nf = 0; nf < 4; nf++) {
            const int r0 = warp_m * 32 + mf * 16 + g;
            const int c0 = warp_n * 32 + nf * 8 + tg * 2;
            Ep[r0 * 129 + c0]       = acc[mf][nf][0];
            Ep[r0 * 129 + c0 + 1]   = acc[mf][nf][1];
            Ep[(r0 + 8) * 129 + c0]     = acc[mf][nf][2];
            Ep[(r0 + 8) * 129 + c0 + 1] = acc[mf][nf][3];
        }
    __syncthreads();

    const int col = tid & 127;
    const int rg = tid >> 7;
    const float biasv = bias[bn * 128 + col];
    if (MODE == 0) {
        const int sel = bn >> 3;
        const int h = ((bn & 7) << 1) + (col >> 6);
        const int dd = col & 63;
        __nv_bfloat16 *dh, *dl;
        if (sel == 0)      { dh = g_Qh; dl = g_Ql; }
        else if (sel == 1) { dh = g_Kh; dl = g_Kl; }
        else               { dh = g_Vh; dl = g_Vl; }
        #pragma unroll 4
        for (int r = 0; r < 32; r++) {
            const int row = rg * 32 + r;
            const int m = bm * 128 + row;
            const int b = m >> 11, t = m & 2047;
            const float v = Ep[row * 129 + col] + biasv;
            const __nv_bfloat16 hb = __float2bfloat16(v);
            const size_t o = (((size_t)(b * H_ + h)) * T_ + t) * D_ + dd;
            dh[o] = hb;
            dl[o] = __float2bfloat16(v - __bfloat162float(hb));
        }
    } else {
        #pragma unroll 4
        for (int r = 0; r < 32; r++) {
            const int row = rg * 32 + r;
            const int m = bm * 128 + row;
            Cout[(size_t)m * C_ + bn * 128 + col] = Ep[row * 129 + col] + biasv;
        }
    }
}

// softcap+mask+exp with fixed max 30: p = exp(-60/(E+1)), E = exp(s/15)
__device__ __forceinline__ float softp(float raw, int qr, int kg, int P) {
    const float sc = raw * 0.125f;
    const float E = __expf(sc * (1.0f / 15.0f));
    const float p = __expf(__fdividef(-60.0f, E + 1.0f));
    const bool valid = ((kg <= qr) && (qr - kg <= WIN_)) || (kg < P);
    return valid ? p : 0.0f;
}

// ---------------------------------------------------------------------------
// HMMA attention: 128 q-rows/CTA, 8 warps (16 q-rows each), 64-key tiles.
// QK^T: Qh*Kh + Qh*Kl + Ql*Kh.  PV: Ph*Vh + Ph*Vl + Pl*Vh.
// P repacked C->A fragments in registers (no smem round trip).
// ---------------------------------------------------------------------------
__global__ __launch_bounds__(256, 2) void attn_kernel(const int* __restrict__ spl)
{
    extern __shared__ __nv_bfloat16 asmem[];
    __nv_bfloat16* Qh = asmem;               // [128][ASP]
    __nv_bfloat16* Ql = Qh + 128 * ASP;
    __nv_bfloat16* Kh = Ql + 128 * ASP;      // [64][ASP]
    __nv_bfloat16* Kl = Kh + 64 * ASP;
    __nv_bfloat16* Vh = Kl + 64 * ASP;       // [64][ASP]
    __nv_bfloat16* Vl = Vh + 64 * ASP;

    const int tid = threadIdx.x;
    const int wid = tid >> 5;      // 0..7
    const int lane = tid & 31;
    const int q0 = blockIdx.x * 128;
    const int h = blockIdx.y;
    const int b = blockIdx.z;
    const size_t bh = (size_t)(b * H_ + h) * T_;
    const int P = spl[b];

    // load Q hi/lo: 128 rows x 8 uint4 each
    for (int i = tid; i < 2048; i += 256) {
        const int arr = i >> 10;            // 0=hi 1=lo
        const int r = (i >> 3) & 127;
        const int c8 = i & 7;
        const __nv_bfloat16* src = (arr == 0 ? g_Qh : g_Ql) + (bh + q0 + r) * D_ + c8 * 8;
        __nv_bfloat16* dst = (arr == 0 ? Qh : Ql) + r * ASP + c8 * 8;
        *(uint4*)dst = *(const uint4*)src;
    }

    // ldmatrix base addresses
    const int a_row = wid * 16 + (lane & 7) + ((lane >> 3) & 1) * 8;
    const int a_kg = (lane >> 4) * 8;
    const uint32_t qh_a = smem_u32(Qh + a_row * ASP + a_kg);
    const uint32_t ql_a = smem_u32(Ql + a_row * ASP + a_kg);
    const int k_row = (lane & 7) + (lane >> 4) * 8;
    const int k_col = ((lane >> 3) & 1) * 8;
    const uint32_t kh_a = smem_u32(Kh + k_row * ASP + k_col);
    const uint32_t kl_a = smem_u32(Kl + k_row * ASP + k_col);
    const int v_row = ((lane >> 3) & 1) * 8 + (lane & 7);
    const int v_col = (lane >> 4) * 8;
    const uint32_t vh_a = smem_u32(Vh + v_row * ASP + v_col);
    const uint32_t vl_a = smem_u32(Vl + v_row * ASP + v_col);

    float o[8][4];
    #pragma unroll
    for (int i = 0; i < 8; i++)
        #pragma unroll
        for (int j = 0; j < 4; j++) o[i][j] = 0.f;
    float lsum0 = 0.f, lsum1 = 0.f;
    const int row0 = q0 + wid * 16 + (lane >> 2);

    for (int kt = 0; kt < T_ / 64; kt++) {
        const int k0 = kt * 64;
        const bool tv = (k0 < P) || ((k0 <= q0 + 127) && (k0 + 63 >= q0 - WIN_));
        if (!tv) continue;   // uniform across block

        __syncthreads();
        // load K,V hi/lo tiles: 4 arrays x 64 rows x 8 uint4
        for (int i = tid; i < 2048; i += 256) {
            const int arr = i >> 9;
            const int r = (i >> 3) & 63;
            const int c8 = i & 7;
            const __nv_bfloat16* src =
                (arr == 0 ? g_Kh : arr == 1 ? g_Kl : arr == 2 ? g_Vh : g_Vl)
                + (bh + k0 + r) * D_ + c8 * 8;
            __nv_bfloat16* dst =
                (arr == 0 ? Kh : arr == 1 ? Kl : arr == 2 ? Vh : Vl) + r * ASP + c8 * 8;
            *(uint4*)dst = *(const uint4*)src;
        }
        __syncthreads();

        // ---- QK^T -> s[8][4] fp32 fragments ----
        float s[8][4];
        #pragma unroll
        for (int i = 0; i < 8; i++)
            #pragma unroll
            for (int j = 0; j < 4; j++) s[i][j] = 0.f;

        #pragma unroll
        for (int kk4 = 0; kk4 < 4; kk4++) {
            uint32_t qa_h[4], qa_l[4];
            LDMX4(qa_h[0], qa_h[1], qa_h[2], qa_h[3], qh_a + kk4 * 32);
            LDMX4(qa_l[0], qa_l[1], qa_l[2], qa_l[3], ql_a + kk4 * 32);
            #pragma unroll
            for (int nf2 = 0; nf2 < 4; nf2++) {
                uint32_t kb_h[4], kb_l[4];
                const uint32_t off = (uint32_t)(nf2 * 16 * ASP) * 2 + kk4 * 32;
                LDMX4(kb_h[0], kb_h[1], kb_h[2], kb_h[3], kh_a + off);
                LDMX4(kb_l[0], kb_l[1], kb_l[2], kb_l[3], kl_a + off);
                MMA16816(s[nf2*2], qa_h[0], qa_h[1], qa_h[2], qa_h[3], kb_h[0], kb_h[1]);
                MMA16816(s[nf2*2], qa_h[0], qa_h[1], qa_h[2], qa_h[3], kb_l[0], kb_l[1]);
                MMA16816(s[nf2*2], qa_l[0], qa_l[1], qa_l[2], qa_l[3], kb_h[0], kb_h[1]);
                MMA16816(s[nf2*2+1], qa_h[0], qa_h[1], qa_h[2], qa_h[3], kb_h[2], kb_h[3]);
                MMA16816(s[nf2*2+1], qa_h[0], qa_h[1], qa_h[2], qa_h[3], kb_l[2], kb_l[3]);
                MMA16816(s[nf2*2+1], qa_l[0], qa_l[1], qa_l[2], qa_l[3], kb_h[2], kb_h[3]);
            }
        }

        // ---- softcap/mask/exp + C->A repack + PV, per k16 group ----
        #pragma unroll
        for (int kc = 0; kc < 4; kc++) {
            uint32_t pah[4], pal[4];
            #pragma unroll
            for (int j = 0; j < 2; j++) {
                const int nf = kc * 2 + j;
                const int cb = k0 + nf * 8 + (lane & 3) * 2;
                const float p0 = softp(s[nf][0], row0,     cb,     P);
                const float p1 = softp(s[nf][1], row0,     cb + 1, P);
                const float p2 = softp(s[nf][2], row0 + 8, cb,     P);
                const float p3 = softp(s[nf][3], row0 + 8, cb + 1, P);
                lsum0 += p0 + p1;
                lsum1 += p2 + p3;
                uint32_t h01, h23;
                PACKBF2(h01, p0, p1);
                PACKBF2(h23, p2, p3);
                pah[j*2]   = h01;
                pah[j*2+1] = h23;
                const float r0 = p0 - __uint_as_float(h01 << 16);
                const float r1 = p1 - __uint_as_float(h01 & 0xFFFF0000u);
                const float r2 = p2 - __uint_as_float(h23 << 16);
                const float r3 = p3 - __uint_as_float(h23 & 0xFFFF0000u);
                uint32_t l01, l23;
                PACKBF2(l01, r0, r1);
                PACKBF2(l23, r2, r3);
                pal[j*2]   = l01;
                pal[j*2+1] = l23;
            }
            #pragma unroll
            for (int nf2 = 0; nf2 < 4; nf2++) {
                uint32_t vb_h[4], vb_l[4];
                const uint32_t off = (uint32_t)(kc * 16 * ASP + nf2 * 16) * 2;
                LDMX4T(vb_h[0], vb_h[1], vb_h[2], vb_h[3], vh_a + off);
                LDMX4T(vb_l[0], vb_l[1], vb_l[2], vb_l[3], vl_a + off);
                MMA16816(o[nf2*2], pah[0], pah[1], pah[2], pah[3], vb_h[0], vb_h[1]);
                MMA16816(o[nf2*2], pah[0], pah[1], pah[2], pah[3], vb_l[0], vb_l[1]);
                MMA16816(o[nf2*2], pal[0], pal[1], pal[2], pal[3], vb_h[0], vb_h[1]);
                MMA16816(o[nf2*2+1], pah[0], pah[1], pah[2], pah[3], vb_h[2], vb_h[3]);
                MMA16816(o[nf2*2+1], pah[0], pah[1], pah[2], pah[3], vb_l[2], vb_l[3]);
                MMA16816(o[nf2*2+1], pal[0], pal[1], pal[2], pal[3], vb_h[2], vb_h[3]);
            }
        }
    }

    // ---- normalize + write bf16 hi/lo ----
    lsum0 += __shfl_xor_sync(0xffffffffu, lsum0, 1);
    lsum0 += __shfl_xor_sync(0xffffffffu, lsum0, 2);
    lsum1 += __shfl_xor_sync(0xffffffffu, lsum1, 1);
    lsum1 += __shfl_xor_sync(0xffffffffu, lsum1, 2);
    const float inv0 = 1.0f / lsum0;
    const float inv1 = 1.0f / lsum1;

    const size_t base0 = ((size_t)(b * T_) + row0) * C_ + h * D_ + (lane & 3) * 2;
    const size_t base1 = base0 + (size_t)8 * C_;
    #pragma unroll
    for (int nf = 0; nf < 8; nf++) {
        const float y0 = o[nf][0] * inv0, y1 = o[nf][1] * inv0;
        const float y2 = o[nf][2] * inv1, y3 = o[nf][3] * inv1;
        uint32_t h01, h23;
        PACKBF2(h01, y0, y1);
        PACKBF2(h23, y2, y3);
        const float r0 = y0 - __uint_as_float(h01 << 16);
        const float r1 = y1 - __uint_as_float(h01 & 0xFFFF0000u);
        const float r2 = y2 - __uint_as_float(h23 << 16);
        const float r3 = y3 - __uint_as_float(h23 & 0xFFFF0000u);
        uint32_t l01, l23;
        PACKBF2(l01, r0, r1);
        PACKBF2(l23, r2, r3);
        *(uint32_t*)(g_ah + base0 + nf * 8) = h01;
        *(uint32_t*)(g_al + base0 + nf * 8) = l01;
        *(uint32_t*)(g_ah + base1 + nf * 8) = h23;
        *(uint32_t*)(g_al + base1 + nf * 8) = l23;
    }
}

// ---------------------------------------------------------------------------
extern "C" void kernel_launch(void* const* d_in, const int* in_sizes, int n_in,
                              void* d_out, int out_size)
{
    (void)in_sizes; (void)n_in; (void)out_size;
    const float* x    = (const float*)d_in[0];
    const int*   spl  = (const int*)  d_in[1];
    const float* Wqkv = (const float*)d_in[2];
    const float* bqkv = (const float*)d_in[3];
    const float* Wprj = (const float*)d_in[4];
    const float* bprj = (const float*)d_in[5];
    float* out = (float*)d_out;

    cudaFuncSetAttribute(attn_kernel,
                         cudaFuncAttributeMaxDynamicSharedMemorySize, ATTN_SMEM);
    cudaFuncSetAttribute(gemm_bf16_kernel<0>,
                         cudaFuncAttributeMaxDynamicSharedMemorySize, GSMEM);
    cudaFuncSetAttribute(gemm_bf16_kernel<1>,
                         cudaFuncAttributeMaxDynamicSharedMemorySize, GSMEM);

    __nv_bfloat16 *xh, *xl, *wqh, *wql, *wph, *wpl, *ah, *al;
    cudaGetSymbolAddress((void**)&xh,  g_xh);  cudaGetSymbolAddress((void**)&xl,  g_xl);
    cudaGetSymbolAddress((void**)&wqh, g_wqh); cudaGetSymbolAddress((void**)&wql, g_wql);
    cudaGetSymbolAddress((void**)&wph, g_wph); cudaGetSymbolAddress((void**)&wpl, g_wpl);
    cudaGetSymbolAddress((void**)&ah,  g_ah);  cudaGetSymbolAddress((void**)&al,  g_al);

    // 0) split fp32 inputs into bf16 hi/lo
    split_kernel<<<(B_*T_*C_/4 + 255)/256, 256>>>(x, xh, xl, B_*T_*C_/4);
    split_kernel<<<(3*C_*C_/4 + 255)/256, 256>>>(Wqkv, wqh, wql, 3*C_*C_/4);
    split_kernel<<<(C_*C_/4 + 255)/256, 256>>>(Wprj, wph, wpl, C_*C_/4);

    // 1) QKV projection (HMMA) -> g_{Q,K,V}{h,l}
    gemm_bf16_kernel<0><<<dim3(3*C_/128, B_*T_/128), 512, GSMEM>>>(
        xh, xl, wqh, wql, bqkv, nullptr);

    // 2) attention (HMMA) -> g_ah/g_al
    attn_kernel<<<dim3(T_/128, H_, B_), 256, ATTN_SMEM>>>(spl);

    // 3) output projection (HMMA) -> d_out
    gemm_bf16_kernel<1><<<dim3(C_/128, B_*T_/128), 512, GSMEM>>>(
        ah, al, wph, wpl, bprj, out);
}